// round 3
// baseline (speedup 1.0000x reference)
#include <cuda_runtime.h>
#include <cuda_bf16.h>
#include <cstdint>

#define D 128
#define MAX_NODES 50000
#define CAP 128
#define XS_STRIDE 132

// ---------------------------------------------------------------------------
// Static device scratch (allocation-free; zero-initialized at module load)
// ---------------------------------------------------------------------------
__device__ float  g_agg[MAX_NODES * D];       // A@x result
__device__ int    g_cnt[MAX_NODES];           // in-degree counters (zeroed by gather after use)
__device__ float2 g_slots[MAX_NODES * CAP];   // (src_as_bits, edge_val) buckets
__device__ uint4  g_wpack[8 * 16 * 8 * 4];    // W bf16 hi/lo frags: [kt][nt][r][c] -> (b0hi,b1hi,b0lo,b1lo)

// ---------------------------------------------------------------------------
// bf16 helpers
// ---------------------------------------------------------------------------
__device__ __forceinline__ uint32_t pack_bf16(float lo_elem, float hi_elem) {
    // cvt.rn.bf16x2.f32 d, a, b  ->  d.hi = bf16(a), d.lo = bf16(b)
    uint32_t r;
    asm("cvt.rn.bf16x2.f32 %0, %1, %2;" : "=r"(r) : "f"(hi_elem), "f"(lo_elem));
    return r;
}

__device__ __forceinline__ void split_pair(float f0, float f1,
                                           uint32_t& hi, uint32_t& lo) {
    hi = pack_bf16(f0, f1);
    float h0 = __uint_as_float(hi << 16);
    float h1 = __uint_as_float(hi & 0xFFFF0000u);
    lo = pack_bf16(f0 - h0, f1 - h1);
}

__device__ __forceinline__ void mma_bf16(float d[4], const uint32_t a[4], const uint32_t b[2]) {
    asm volatile(
        "mma.sync.aligned.m16n8k16.row.col.f32.bf16.bf16.f32 "
        "{%0,%1,%2,%3}, {%4,%5,%6,%7}, {%8,%9}, {%0,%1,%2,%3};"
        : "+f"(d[0]), "+f"(d[1]), "+f"(d[2]), "+f"(d[3])
        : "r"(a[0]), "r"(a[1]), "r"(a[2]), "r"(a[3]), "r"(b[0]), "r"(b[1]));
}

// ---------------------------------------------------------------------------
// K0: pack W into bf16 hi/lo mma fragments, exact m16n8k16 row.col B layout.
// Entry i -> c=i&3, r=(i>>2)&7, nt=(i>>5)&15, kt=i>>9.
// B frag for (kt,nt,thread r,c): b0 = W[k0+2c, n], W[k0+2c+1, n]
//                                b1 = W[k0+2c+8, n], W[k0+2c+9, n],  n = nt*8+r
// ---------------------------------------------------------------------------
__global__ void gcn_wpack_kernel(const float* __restrict__ w)
{
    int i = blockIdx.x * blockDim.x + threadIdx.x;
    if (i >= 8 * 16 * 8 * 4) return;
    int c  = i & 3;
    int r  = (i >> 2) & 7;
    int nt = (i >> 5) & 15;
    int kt = i >> 9;
    int n  = nt * 8 + r;
    int k  = kt * 16 + 2 * c;

    float w00 = w[(k    ) * D + n];
    float w01 = w[(k + 1) * D + n];
    float w10 = w[(k + 8) * D + n];
    float w11 = w[(k + 9) * D + n];

    uint4 v;
    split_pair(w00, w01, v.x, v.z);   // b0 hi / lo
    split_pair(w10, w11, v.y, v.w);   // b1 hi / lo
    g_wpack[i] = v;
}

// ---------------------------------------------------------------------------
// K1: bucket-CSR fill
// ---------------------------------------------------------------------------
__global__ void gcn_fill_kernel(const int* __restrict__ src,
                                const int* __restrict__ dst,
                                const float* __restrict__ ev,
                                int n_edges)
{
    int e = blockIdx.x * blockDim.x + threadIdx.x;
    if (e >= n_edges) return;
    int d = dst[e];
    int c = atomicAdd(&g_cnt[d], 1);
    if (c < CAP)
        g_slots[(size_t)d * CAP + c] = make_float2(__int_as_float(src[e]), ev[e]);
}

// ---------------------------------------------------------------------------
// K2: gather-aggregate (L2-bandwidth bound; ~410MB of x-row gathers).
// One warp per node, lane = 4 dims. Resets g_cnt for the next graph replay.
// ---------------------------------------------------------------------------
__global__ void __launch_bounds__(256) gcn_gather_kernel(
    const float* __restrict__ x, int n_nodes)
{
    int node = blockIdx.x * 8 + (threadIdx.x >> 5);
    int lane = threadIdx.x & 31;
    if (node >= n_nodes) return;

    int cnt = g_cnt[node];
    if (lane == 0) g_cnt[node] = 0;          // reset for next call (replay-safe)
    if (cnt > CAP) cnt = CAP;

    const size_t base = (size_t)node * CAP;
    const float4* __restrict__ x4 = (const float4*)x;

    float4 acc = make_float4(0.f, 0.f, 0.f, 0.f);

    int i = 0;
    for (; i + 3 < cnt; i += 4) {
        float2 sv0 = g_slots[base + i];
        float2 sv1 = g_slots[base + i + 1];
        float2 sv2 = g_slots[base + i + 2];
        float2 sv3 = g_slots[base + i + 3];
        float4 v0 = __ldg(&x4[(size_t)__float_as_int(sv0.x) * 32 + lane]);
        float4 v1 = __ldg(&x4[(size_t)__float_as_int(sv1.x) * 32 + lane]);
        float4 v2 = __ldg(&x4[(size_t)__float_as_int(sv2.x) * 32 + lane]);
        float4 v3 = __ldg(&x4[(size_t)__float_as_int(sv3.x) * 32 + lane]);
        acc.x += sv0.y * v0.x; acc.y += sv0.y * v0.y; acc.z += sv0.y * v0.z; acc.w += sv0.y * v0.w;
        acc.x += sv1.y * v1.x; acc.y += sv1.y * v1.y; acc.z += sv1.y * v1.z; acc.w += sv1.y * v1.w;
        acc.x += sv2.y * v2.x; acc.y += sv2.y * v2.y; acc.z += sv2.y * v2.z; acc.w += sv2.y * v2.w;
        acc.x += sv3.y * v3.x; acc.y += sv3.y * v3.y; acc.z += sv3.y * v3.z; acc.w += sv3.y * v3.w;
    }
    for (; i < cnt; i++) {
        float2 sv = g_slots[base + i];
        float4 v = __ldg(&x4[(size_t)__float_as_int(sv.x) * 32 + lane]);
        acc.x += sv.y * v.x; acc.y += sv.y * v.y; acc.z += sv.y * v.z; acc.w += sv.y * v.w;
    }

    ((float4*)g_agg)[(size_t)node * 32 + lane] = acc;
}

// ---------------------------------------------------------------------------
// K3: out = agg @ W + bias.  bf16 2-term split, mma.m16n8k16.
// Block = 4 warps, tile M=64 N=128 K=128; each warp owns 16 rows.
// W frags: one coalesced LDG.128 per (kt,nt) from the 64KB L1-resident table.
// ---------------------------------------------------------------------------
__global__ void __launch_bounds__(128) gcn_gemm_bf16_kernel(
    const float* __restrict__ bias,
    float* __restrict__ out,
    int n_nodes)
{
    __shared__ float xs[64 * XS_STRIDE];

    const int tid   = threadIdx.x;
    const int warp  = tid >> 5;
    const int lane  = tid & 31;
    const int node0 = blockIdx.x * 64;

    // stage agg tile [64][128] into padded shared
    {
        const float4* __restrict__ a4 = (const float4*)g_agg;
        #pragma unroll
        for (int it = 0; it < 16; it++) {
            int linear = tid + it * 128;
            int rr = linear >> 5;
            int c4 = linear & 31;
            int node = node0 + rr;
            float4 v = (node < n_nodes) ? a4[(size_t)node * 32 + c4]
                                        : make_float4(0.f, 0.f, 0.f, 0.f);
            float* p = &xs[rr * XS_STRIDE + c4 * 4];
            *(float2*)(p)     = make_float2(v.x, v.y);
            *(float2*)(p + 2) = make_float2(v.z, v.w);
        }
    }
    __syncthreads();

    const int r = lane >> 2;
    const int c = lane & 3;
    const int warp_m = warp * 16;
    const uint4* __restrict__ wp = g_wpack + lane;   // lane == r*4+c

    float acc[16][4];
    #pragma unroll
    for (int nt = 0; nt < 16; nt++) {
        acc[nt][0] = 0.f; acc[nt][1] = 0.f; acc[nt][2] = 0.f; acc[nt][3] = 0.f;
    }

    #pragma unroll 1
    for (int kt = 0; kt < 8; kt++) {
        const int k0 = kt * 16;

        // A fragments: rows warp_m+r / +8; cols 2c,2c+1 and 2c+8,2c+9
        float2 x00 = *(const float2*)&xs[(warp_m + r)     * XS_STRIDE + k0 + 2 * c];
        float2 x10 = *(const float2*)&xs[(warp_m + r + 8) * XS_STRIDE + k0 + 2 * c];
        float2 x01 = *(const float2*)&xs[(warp_m + r)     * XS_STRIDE + k0 + 2 * c + 8];
        float2 x11 = *(const float2*)&xs[(warp_m + r + 8) * XS_STRIDE + k0 + 2 * c + 8];

        uint32_t a_hi[4], a_lo[4];
        split_pair(x00.x, x00.y, a_hi[0], a_lo[0]);
        split_pair(x10.x, x10.y, a_hi[1], a_lo[1]);
        split_pair(x01.x, x01.y, a_hi[2], a_lo[2]);
        split_pair(x11.x, x11.y, a_hi[3], a_lo[3]);

        #pragma unroll
        for (int nt = 0; nt < 16; nt++) {
            uint4 wv = __ldg(&wp[(kt * 16 + nt) * 32]);
            uint32_t b_hi[2] = {wv.x, wv.y};
            uint32_t b_lo[2] = {wv.z, wv.w};
            mma_bf16(acc[nt], a_hi, b_hi);
            mma_bf16(acc[nt], a_lo, b_hi);
            mma_bf16(acc[nt], a_hi, b_lo);
        }
    }

    // epilogue: + bias, store
    const int row0 = node0 + warp_m + r;
    const int row1 = row0 + 8;
    #pragma unroll
    for (int nt = 0; nt < 16; nt++) {
        const int col0 = nt * 8 + 2 * c;
        float2 bv = __ldg((const float2*)&bias[col0]);
        if (row0 < n_nodes) {
            *(float2*)&out[(size_t)row0 * D + col0] =
                make_float2(acc[nt][0] + bv.x, acc[nt][1] + bv.y);
        }
        if (row1 < n_nodes) {
            *(float2*)&out[(size_t)row1 * D + col0] =
                make_float2(acc[nt][2] + bv.x, acc[nt][3] + bv.y);
        }
    }
}

// ---------------------------------------------------------------------------
// Launch wrapper.  Inputs per metadata order:
//   0: x [N,128] f32   1: weight [128,128] f32   2: bias [128] f32
//   3: src [E] i32     4: dst [E] i32            5: edge_vals [E] f32
// ---------------------------------------------------------------------------
extern "C" void kernel_launch(void* const* d_in, const int* in_sizes, int n_in,
                              void* d_out, int out_size)
{
    const float* x    = (const float*)d_in[0];
    const float* w    = (const float*)d_in[1];
    const float* bias = (const float*)d_in[2];
    const int*   src  = (const int*)d_in[3];
    const int*   dst  = (const int*)d_in[4];
    const float* ev   = (const float*)d_in[5];
    float* out = (float*)d_out;

    const int n_nodes = in_sizes[0] / D;
    const int n_edges = in_sizes[3];

    gcn_wpack_kernel<<<(8 * 16 * 8 * 4 + 255) / 256, 256>>>(w);
    gcn_fill_kernel<<<(n_edges + 255) / 256, 256>>>(src, dst, ev, n_edges);
    gcn_gather_kernel<<<(n_nodes + 7) / 8, 256>>>(x, n_nodes);
    gcn_gemm_bf16_kernel<<<(n_nodes + 63) / 64, 128>>>(bias, out, n_nodes);
}

// round 4
// speedup vs baseline: 1.0752x; 1.0752x over previous
#include <cuda_runtime.h>
#include <cuda_bf16.h>
#include <cstdint>

#define D 128
#define MAX_NODES 50000
#define CAP 128
#define XS_STRIDE 132

// ---------------------------------------------------------------------------
// Static device scratch (allocation-free; zero-initialized at module load)
// ---------------------------------------------------------------------------
__device__ float  g_agg[MAX_NODES * D];       // A@x result
__device__ int    g_cnt[MAX_NODES];           // in-degree counters (reset by gather)
__device__ float2 g_slots[MAX_NODES * CAP];   // (src_as_bits, edge_val) buckets
__device__ uint4  g_wpack[8 * 16 * 8 * 4];    // W bf16 hi/lo frags [kt][nt][r][c]

// ---------------------------------------------------------------------------
// bf16 helpers
// ---------------------------------------------------------------------------
__device__ __forceinline__ uint32_t pack_bf16(float lo_elem, float hi_elem) {
    uint32_t r;
    asm("cvt.rn.bf16x2.f32 %0, %1, %2;" : "=r"(r) : "f"(hi_elem), "f"(lo_elem));
    return r;
}

__device__ __forceinline__ void split_pair(float f0, float f1,
                                           uint32_t& hi, uint32_t& lo) {
    hi = pack_bf16(f0, f1);
    float h0 = __uint_as_float(hi << 16);
    float h1 = __uint_as_float(hi & 0xFFFF0000u);
    lo = pack_bf16(f0 - h0, f1 - h1);
}

__device__ __forceinline__ void mma_bf16(float d[4], const uint32_t a[4], const uint32_t b[2]) {
    asm volatile(
        "mma.sync.aligned.m16n8k16.row.col.f32.bf16.bf16.f32 "
        "{%0,%1,%2,%3}, {%4,%5,%6,%7}, {%8,%9}, {%0,%1,%2,%3};"
        : "+f"(d[0]), "+f"(d[1]), "+f"(d[2]), "+f"(d[3])
        : "r"(a[0]), "r"(a[1]), "r"(a[2]), "r"(a[3]), "r"(b[0]), "r"(b[1]));
}

// ---------------------------------------------------------------------------
// K0: pack W into bf16 hi/lo mma fragments (m16n8k16 row.col B layout)
// ---------------------------------------------------------------------------
__global__ void gcn_wpack_kernel(const float* __restrict__ w)
{
    int i = blockIdx.x * blockDim.x + threadIdx.x;
    if (i >= 8 * 16 * 8 * 4) return;
    int c  = i & 3;
    int r  = (i >> 2) & 7;
    int nt = (i >> 5) & 15;
    int kt = i >> 9;
    int n  = nt * 8 + r;
    int k  = kt * 16 + 2 * c;

    float w00 = w[(k    ) * D + n];
    float w01 = w[(k + 1) * D + n];
    float w10 = w[(k + 8) * D + n];
    float w11 = w[(k + 9) * D + n];

    uint4 v;
    split_pair(w00, w01, v.x, v.z);
    split_pair(w10, w11, v.y, v.w);
    g_wpack[i] = v;
}

// ---------------------------------------------------------------------------
// K1: bucket-CSR fill
// ---------------------------------------------------------------------------
__global__ void gcn_fill_kernel(const int* __restrict__ src,
                                const int* __restrict__ dst,
                                const float* __restrict__ ev,
                                int n_edges)
{
    int e = blockIdx.x * blockDim.x + threadIdx.x;
    if (e >= n_edges) return;
    int d = dst[e];
    int c = atomicAdd(&g_cnt[d], 1);
    if (c < CAP)
        g_slots[(size_t)d * CAP + c] = make_float2(__int_as_float(src[e]), ev[e]);
}

// ---------------------------------------------------------------------------
// K2: gather-aggregate (L2-bandwidth bound).  R2-proven unroll-2 loop.
// One warp per node, lane = 4 dims.  Resets g_cnt for the next replay.
// ---------------------------------------------------------------------------
__global__ void __launch_bounds__(256) gcn_gather_kernel(
    const float* __restrict__ x, int n_nodes)
{
    int node = blockIdx.x * 8 + (threadIdx.x >> 5);
    int lane = threadIdx.x & 31;
    if (node >= n_nodes) return;

    int cnt = g_cnt[node];
    if (lane == 0) g_cnt[node] = 0;
    if (cnt > CAP) cnt = CAP;

    const size_t base = (size_t)node * CAP;
    const float4* __restrict__ x4 = (const float4*)x;

    float4 acc = make_float4(0.f, 0.f, 0.f, 0.f);

    int i = 0;
    for (; i + 1 < cnt; i += 2) {
        float2 sv0 = g_slots[base + i];
        float2 sv1 = g_slots[base + i + 1];
        int s0 = __float_as_int(sv0.x);
        int s1 = __float_as_int(sv1.x);
        float4 v0 = __ldg(&x4[(size_t)s0 * 32 + lane]);
        float4 v1 = __ldg(&x4[(size_t)s1 * 32 + lane]);
        acc.x += sv0.y * v0.x; acc.y += sv0.y * v0.y;
        acc.z += sv0.y * v0.z; acc.w += sv0.y * v0.w;
        acc.x += sv1.y * v1.x; acc.y += sv1.y * v1.y;
        acc.z += sv1.y * v1.z; acc.w += sv1.y * v1.w;
    }
    if (i < cnt) {
        float2 sv = g_slots[base + i];
        int s = __float_as_int(sv.x);
        float4 v = __ldg(&x4[(size_t)s * 32 + lane]);
        acc.x += sv.y * v.x; acc.y += sv.y * v.y;
        acc.z += sv.y * v.z; acc.w += sv.y * v.w;
    }

    ((float4*)g_agg)[(size_t)node * 32 + lane] = acc;
}

// ---------------------------------------------------------------------------
// K3: out = agg @ W + bias.  bf16 2-term split, mma.m16n8k16.
// Block = 256 threads (8 warps), tile M=64 N=128 K=128.
// Warp pair shares 16 rows; each warp covers one N-half (8 nt).
// acc = 32 regs/thread -> ~64 regs total -> ~2x occupancy vs R3.
// ---------------------------------------------------------------------------
__global__ void __launch_bounds__(256) gcn_gemm_bf16_kernel(
    const float* __restrict__ bias,
    float* __restrict__ out,
    int n_nodes)
{
    __shared__ float xs[64 * XS_STRIDE];

    const int tid   = threadIdx.x;
    const int warp  = tid >> 5;
    const int lane  = tid & 31;
    const int node0 = blockIdx.x * 64;

    // stage agg tile [64][128] into padded shared
    {
        const float4* __restrict__ a4 = (const float4*)g_agg;
        #pragma unroll
        for (int it = 0; it < 8; it++) {
            int linear = tid + it * 256;          // 0..2047 float4 granules
            int rr = linear >> 5;
            int c4 = linear & 31;
            int node = node0 + rr;
            float4 v = (node < n_nodes) ? a4[(size_t)node * 32 + c4]
                                        : make_float4(0.f, 0.f, 0.f, 0.f);
            float* p = &xs[rr * XS_STRIDE + c4 * 4];
            *(float2*)(p)     = make_float2(v.x, v.y);
            *(float2*)(p + 2) = make_float2(v.z, v.w);
        }
    }
    __syncthreads();

    const int r  = lane >> 2;
    const int c  = lane & 3;
    const int rg = warp >> 1;          // row group 0..3 -> rows rg*16..+16
    const int nh = warp & 1;           // N half: nt in [nh*8, nh*8+8)
    const int warp_m = rg * 16;
    const uint4* __restrict__ wp = g_wpack + lane;

    float acc[8][4];
    #pragma unroll
    for (int nt = 0; nt < 8; nt++) {
        acc[nt][0] = 0.f; acc[nt][1] = 0.f; acc[nt][2] = 0.f; acc[nt][3] = 0.f;
    }

    #pragma unroll 1
    for (int kt = 0; kt < 8; kt++) {
        const int k0 = kt * 16;

        float2 x00 = *(const float2*)&xs[(warp_m + r)     * XS_STRIDE + k0 + 2 * c];
        float2 x10 = *(const float2*)&xs[(warp_m + r + 8) * XS_STRIDE + k0 + 2 * c];
        float2 x01 = *(const float2*)&xs[(warp_m + r)     * XS_STRIDE + k0 + 2 * c + 8];
        float2 x11 = *(const float2*)&xs[(warp_m + r + 8) * XS_STRIDE + k0 + 2 * c + 8];

        uint32_t a_hi[4], a_lo[4];
        split_pair(x00.x, x00.y, a_hi[0], a_lo[0]);
        split_pair(x10.x, x10.y, a_hi[1], a_lo[1]);
        split_pair(x01.x, x01.y, a_hi[2], a_lo[2]);
        split_pair(x11.x, x11.y, a_hi[3], a_lo[3]);

        #pragma unroll
        for (int ntl = 0; ntl < 8; ntl++) {
            int nt = nh * 8 + ntl;
            uint4 wv = __ldg(&wp[(kt * 16 + nt) * 32]);
            uint32_t b_hi[2] = {wv.x, wv.y};
            uint32_t b_lo[2] = {wv.z, wv.w};
            mma_bf16(acc[ntl], a_hi, b_hi);
            mma_bf16(acc[ntl], a_lo, b_hi);
            mma_bf16(acc[ntl], a_hi, b_lo);
        }
    }

    // epilogue: + bias, store
    const int row0 = node0 + warp_m + r;
    const int row1 = row0 + 8;
    #pragma unroll
    for (int ntl = 0; ntl < 8; ntl++) {
        const int col0 = (nh * 8 + ntl) * 8 + 2 * c;
        float2 bv = __ldg((const float2*)&bias[col0]);
        if (row0 < n_nodes) {
            *(float2*)&out[(size_t)row0 * D + col0] =
                make_float2(acc[ntl][0] + bv.x, acc[ntl][1] + bv.y);
        }
        if (row1 < n_nodes) {
            *(float2*)&out[(size_t)row1 * D + col0] =
                make_float2(acc[ntl][2] + bv.x, acc[ntl][3] + bv.y);
        }
    }
}

// ---------------------------------------------------------------------------
// Launch wrapper.  Inputs per metadata order:
//   0: x [N,128] f32   1: weight [128,128] f32   2: bias [128] f32
//   3: src [E] i32     4: dst [E] i32            5: edge_vals [E] f32
// ---------------------------------------------------------------------------
extern "C" void kernel_launch(void* const* d_in, const int* in_sizes, int n_in,
                              void* d_out, int out_size)
{
    const float* x    = (const float*)d_in[0];
    const float* w    = (const float*)d_in[1];
    const float* bias = (const float*)d_in[2];
    const int*   src  = (const int*)d_in[3];
    const int*   dst  = (const int*)d_in[4];
    const float* ev   = (const float*)d_in[5];
    float* out = (float*)d_out;

    const int n_nodes = in_sizes[0] / D;
    const int n_edges = in_sizes[3];

    gcn_wpack_kernel<<<(8 * 16 * 8 * 4 + 255) / 256, 256>>>(w);
    gcn_fill_kernel<<<(n_edges + 255) / 256, 256>>>(src, dst, ev, n_edges);
    gcn_gather_kernel<<<(n_nodes + 7) / 8, 256>>>(x, n_nodes);
    gcn_gemm_bf16_kernel<<<(n_nodes + 63) / 64, 256>>>(bias, out, n_nodes);
}